// round 13
// baseline (speedup 1.0000x reference)
#include <cuda_runtime.h>

// Problem constants (from reference)
#define VOCAB      30000
#define N_PRE      20000
#define VEC_DIM    300
#define INPUT_SIZE 10000   // VOCAB - N_PRE
#define HIDDEN     256
#define OUT_DIM    556     // VEC_DIM + HIDDEN
#define N_TOKENS   4096    // 8 * 512
#define VEC4       (VEC_DIM / 4)   // 75 float4 per vector row

#define VEC_ITEMS  (N_TOKENS * VEC4)          // 307200 float4 copy items
#define VEC_BLOCKS ((VEC_ITEMS + 255) / 256)  // 1200
#define TOTAL_BLOCKS (N_TOKENS + VEC_BLOCKS)  // 5296

// Single fused kernel, two block roles selected by blockIdx.x:
//  [0, 4096):        hidden part, block = token, thread = h.
//                    out[tok][300+h] = b[h] + (t>=N_PRE ? W[h*10000+(t-N_PRE)] : 0)
//  [4096, 5296):     vector part, flat item-per-thread float4 copy.
//                    out[tok][0:300] = (t<N_PRE ? vectors[t] : 0)
// Both access patterns are co-resident chip-wide: the W gather (random 32B
// sectors) and the streaming row copy interleave, maximizing in-flight memory.
__global__ __launch_bounds__(256)
void encoder_fused(const int* __restrict__ batch,
                   const float* __restrict__ vectors,
                   const float* __restrict__ W,
                   const float* __restrict__ b,
                   float* __restrict__ out)
{
    const int bid = blockIdx.x;
    const int tid = threadIdx.x;

    if (bid < N_TOKENS) {
        // ---- hidden: one block per token ----
        const int t = batch[bid];                 // same addr block-wide -> broadcast
        float w = 0.f;
        if (t >= N_PRE)                           // gather issued ASAP
            w = W[(size_t)tid * INPUT_SIZE + (t - N_PRE)];
        const float bias = b[tid];                // independent, overlaps gather
        out[(size_t)bid * OUT_DIM + VEC_DIM + tid] = bias + w;
    } else {
        // ---- vector: flat float4 copy ----
        const int k = (bid - N_TOKENS) * 256 + tid;   // 0 .. 307199
        if (k < VEC_ITEMS) {
            const int tok = k / VEC4;
            const int q   = k - tok * VEC4;
            const int t   = batch[tok];           // ~2-3 distinct per warp
            float4 v = make_float4(0.f, 0.f, 0.f, 0.f);
            if (t < N_PRE)
                v = reinterpret_cast<const float4*>(
                        vectors + (size_t)t * VEC_DIM)[q];
            // out row base = tok*2224 B -> 16B aligned
            reinterpret_cast<float4*>(out + (size_t)tok * OUT_DIM)[q] = v;
        }
    }
}

extern "C" void kernel_launch(void* const* d_in, const int* in_sizes, int n_in,
                              void* d_out, int out_size)
{
    const int*   batch   = (const int*)  d_in[0];
    const float* vectors = (const float*)d_in[1];
    const float* W       = (const float*)d_in[2];
    const float* b       = (const float*)d_in[3];
    float*       out     = (float*)d_out;

    encoder_fused<<<TOTAL_BLOCKS, 256>>>(batch, vectors, W, b, out);
}